// round 3
// baseline (speedup 1.0000x reference)
#include <cuda_runtime.h>
#include <cstdint>
#include <math.h>

#define NFEAT 512
#define NHID  256
#define NCLS  40
#define NMAX  100000
#define EMAX  3200000

// ---- scratch (static device globals; allocation-free) ----
__device__ __align__(16) float g_deg [NMAX];
__device__ __align__(16) float g_dinv[NMAX];
__device__ __align__(16) float g_h1  [(size_t)NMAX * NHID];   // x @ W1
__device__ __align__(16) float g_agg1[(size_t)NMAX * NHID];   // aggregated layer-1
__device__ __align__(16) float g_h2  [(size_t)NMAX * NCLS];   // relu(agg1) @ W2
__device__ int g_src[EMAX];
__device__ int g_dst[EMAX];
__device__ int g_is64;

// ---------------------------------------------------------------------------
// edge dtype detection + normalization to int32
// ---------------------------------------------------------------------------
__global__ void k_detect(const void* __restrict__ ei) {
    const long long* p = (const long long*)ei;
    int i64 = 1;
    #pragma unroll
    for (int k = 0; k < 8; k++) {
        long long v = p[k];
        if (v < 0 || v >= NMAX) { i64 = 0; break; }
    }
    g_is64 = i64;
}

__global__ void k_convert(const void* __restrict__ ei, int E) {
    int e = blockIdx.x * blockDim.x + threadIdx.x;
    if (e >= E) return;
    if (g_is64) {
        const long long* p = (const long long*)ei;
        g_src[e] = (int)p[e];
        g_dst[e] = (int)p[E + e];
    } else {
        const int* p = (const int*)ei;
        g_src[e] = p[e];
        g_dst[e] = p[E + e];
    }
}

// ---------------------------------------------------------------------------
// degree / normalization
// ---------------------------------------------------------------------------
__global__ void k_deg_init(int n) {
    int i = blockIdx.x * blockDim.x + threadIdx.x;
    if (i < n) g_deg[i] = 1.0f;                 // self-loop
}

__global__ void k_deg_count(int E) {
    int e = blockIdx.x * blockDim.x + threadIdx.x;
    if (e < E) atomicAdd(&g_deg[g_dst[e]], 1.0f);
}

__global__ void k_dinv(int n) {
    int i = blockIdx.x * blockDim.x + threadIdx.x;
    if (i < n) g_dinv[i] = rsqrtf(g_deg[i]);    // deg >= 1 always
}

// ---------------------------------------------------------------------------
// SGEMM1: h1 = x @ W1   (M x 512) @ (512 x 256), fp32, 128x128x8 tiles
// ---------------------------------------------------------------------------
__global__ __launch_bounds__(256) void k_sgemm1(const float* __restrict__ A,
                                                const float* __restrict__ B,
                                                int M) {
    const int K = NFEAT, N = NHID;
    __shared__ float As[8][128];
    __shared__ float Bs[8][128];

    int tid = threadIdx.x;
    int bm = blockIdx.x * 128;
    int bn = blockIdx.y * 128;

    int tx = tid % 16;            // 16x16 thread grid, 8x8 microtile
    int ty = tid / 16;

    int aRow = tid >> 1;          // 0..127
    int aCol = (tid & 1) * 4;     // 0 or 4
    int bRow = tid >> 5;          // 0..7
    int bCol = (tid & 31) * 4;    // 0..124

    float acc[8][8];
    #pragma unroll
    for (int i = 0; i < 8; i++)
        #pragma unroll
        for (int j = 0; j < 8; j++) acc[i][j] = 0.0f;

    for (int k0 = 0; k0 < K; k0 += 8) {
        float4 av;
        int gr = bm + aRow;
        if (gr < M) av = *(const float4*)(A + (size_t)gr * K + k0 + aCol);
        else        av = make_float4(0.f, 0.f, 0.f, 0.f);
        As[aCol + 0][aRow] = av.x;
        As[aCol + 1][aRow] = av.y;
        As[aCol + 2][aRow] = av.z;
        As[aCol + 3][aRow] = av.w;

        float4 bv = *(const float4*)(B + (size_t)(k0 + bRow) * N + bn + bCol);
        *(float4*)&Bs[bRow][bCol] = bv;
        __syncthreads();

        #pragma unroll
        for (int kk = 0; kk < 8; kk++) {
            float ar[8], br[8];
            #pragma unroll
            for (int i = 0; i < 8; i++) ar[i] = As[kk][ty * 8 + i];
            #pragma unroll
            for (int j = 0; j < 8; j++) br[j] = Bs[kk][tx * 8 + j];
            #pragma unroll
            for (int i = 0; i < 8; i++)
                #pragma unroll
                for (int j = 0; j < 8; j++)
                    acc[i][j] = fmaf(ar[i], br[j], acc[i][j]);
        }
        __syncthreads();
    }

    #pragma unroll
    for (int i = 0; i < 8; i++) {
        int r = bm + ty * 8 + i;
        if (r >= M) continue;
        #pragma unroll
        for (int j = 0; j < 8; j += 4) {
            float4 v = make_float4(acc[i][j], acc[i][j + 1], acc[i][j + 2], acc[i][j + 3]);
            *(float4*)(g_h1 + (size_t)r * N + bn + tx * 8 + j) = v;
        }
    }
}

// ---------------------------------------------------------------------------
// agg1[i,:] = b1 + h1[i,:] * dinv[i]^2   (self-loop + bias folded in)
// ---------------------------------------------------------------------------
__global__ void k_init_agg1(const float* __restrict__ b1, int n) {
    int t = blockIdx.x * blockDim.x + threadIdx.x;
    int total = n * (NHID / 4);
    if (t >= total) return;
    int i  = t >> 6;      // /64
    int j4 = t & 63;
    float w = g_dinv[i]; w *= w;
    float4 hv = *(const float4*)(g_h1 + (size_t)i * NHID + j4 * 4);
    float4 bv = *(const float4*)(b1 + j4 * 4);
    float4 o;
    o.x = fmaf(hv.x, w, bv.x);
    o.y = fmaf(hv.y, w, bv.y);
    o.z = fmaf(hv.z, w, bv.z);
    o.w = fmaf(hv.w, w, bv.w);
    *(float4*)(g_agg1 + (size_t)i * NHID + j4 * 4) = o;
}

__device__ __forceinline__ void red_add_v4(float* p, float4 v) {
    asm volatile("red.global.add.v4.f32 [%0], {%1,%2,%3,%4};"
                 :: "l"(p), "f"(v.x), "f"(v.y), "f"(v.z), "f"(v.w)
                 : "memory");
}

// ---------------------------------------------------------------------------
// scatter1: one warp per edge, 256 floats = 64 float4 = 2 float4/lane
// ---------------------------------------------------------------------------
__global__ __launch_bounds__(256) void k_scatter1(int E) {
    int wid  = (blockIdx.x * blockDim.x + threadIdx.x) >> 5;
    int lane = threadIdx.x & 31;
    if (wid >= E) return;
    int s = 0, d = 0;
    if (lane == 0) { s = g_src[wid]; d = g_dst[wid]; }
    s = __shfl_sync(0xffffffffu, s, 0);
    d = __shfl_sync(0xffffffffu, d, 0);
    float nrm = g_dinv[s] * g_dinv[d];
    const float4* hp = (const float4*)(g_h1 + (size_t)s * NHID);
    float* op = g_agg1 + (size_t)d * NHID;
    #pragma unroll
    for (int r = 0; r < 2; r++) {
        int j = lane + r * 32;
        float4 v = hp[j];
        v.x *= nrm; v.y *= nrm; v.z *= nrm; v.w *= nrm;
        red_add_v4(op + j * 4, v);
    }
}

// ---------------------------------------------------------------------------
// GEMM2 (relu fused): h2 = relu(agg1) @ W2   (256 -> 40), warp per node
// ---------------------------------------------------------------------------
__global__ __launch_bounds__(256) void k_gemm2(const float* __restrict__ W2, int n) {
    __shared__ float Ws[NHID * NCLS];   // 40 KB
    int tid = threadIdx.x;
    for (int t = tid; t < NHID * NCLS; t += blockDim.x) Ws[t] = W2[t];
    __syncthreads();

    int warp = (blockIdx.x * blockDim.x + tid) >> 5;
    int lane = tid & 31;
    if (warp >= n) return;

    const float* row = g_agg1 + (size_t)warp * NHID;
    float acc0 = 0.f, acc1 = 0.f;
    for (int k0 = 0; k0 < NHID; k0 += 32) {
        float a = fmaxf(row[k0 + lane], 0.f);
        #pragma unroll
        for (int kk = 0; kk < 32; kk++) {
            float av = __shfl_sync(0xffffffffu, a, kk);
            acc0 = fmaf(av, Ws[(k0 + kk) * NCLS + lane], acc0);
            if (lane < 8)
                acc1 = fmaf(av, Ws[(k0 + kk) * NCLS + 32 + lane], acc1);
        }
    }
    g_h2[(size_t)warp * NCLS + lane] = acc0;
    if (lane < 8) g_h2[(size_t)warp * NCLS + 32 + lane] = acc1;
}

// ---------------------------------------------------------------------------
// out[i,:] = b2 + h2[i,:] * dinv[i]^2
// ---------------------------------------------------------------------------
__global__ void k_init_out(const float* __restrict__ b2, float* __restrict__ out, int n) {
    int t = blockIdx.x * blockDim.x + threadIdx.x;
    int total = n * 10;               // 40 floats = 10 float4
    if (t >= total) return;
    int i = t / 10;
    int c = t - i * 10;
    float w = g_dinv[i]; w *= w;
    float4 hv = *(const float4*)(g_h2 + (size_t)i * NCLS + c * 4);
    float4 bv = *(const float4*)(b2 + c * 4);
    float4 o;
    o.x = fmaf(hv.x, w, bv.x);
    o.y = fmaf(hv.y, w, bv.y);
    o.z = fmaf(hv.z, w, bv.z);
    o.w = fmaf(hv.w, w, bv.w);
    *(float4*)(out + (size_t)i * NCLS + c * 4) = o;
}

// ---------------------------------------------------------------------------
// scatter2: thread per (edge, float4-chunk), 10 chunks per edge
// ---------------------------------------------------------------------------
__global__ __launch_bounds__(256) void k_scatter2(float* __restrict__ out, int E) {
    int t = blockIdx.x * blockDim.x + threadIdx.x;
    if (t >= E * 10) return;
    int e = t / 10;
    int c = t - e * 10;
    int s = g_src[e];
    int d = g_dst[e];
    float nrm = g_dinv[s] * g_dinv[d];
    float4 v = *(const float4*)(g_h2 + (size_t)s * NCLS + c * 4);
    v.x *= nrm; v.y *= nrm; v.z *= nrm; v.w *= nrm;
    red_add_v4(out + (size_t)d * NCLS + c * 4, v);
}

// ---------------------------------------------------------------------------
// log_softmax over 40 classes, warp per node (in-place)
// ---------------------------------------------------------------------------
__global__ __launch_bounds__(256) void k_logsoftmax(float* __restrict__ out, int n) {
    int warp = (blockIdx.x * blockDim.x + threadIdx.x) >> 5;
    int lane = threadIdx.x & 31;
    if (warp >= n) return;
    float* row = out + (size_t)warp * NCLS;
    float v0 = row[lane];
    float v1 = (lane < 8) ? row[32 + lane] : -INFINITY;
    float m = fmaxf(v0, v1);
    #pragma unroll
    for (int off = 16; off > 0; off >>= 1)
        m = fmaxf(m, __shfl_xor_sync(0xffffffffu, m, off));
    float e = __expf(v0 - m) + ((lane < 8) ? __expf(v1 - m) : 0.f);
    #pragma unroll
    for (int off = 16; off > 0; off >>= 1)
        e += __shfl_xor_sync(0xffffffffu, e, off);
    float lse = m + __logf(e);
    row[lane] = v0 - lse;
    if (lane < 8) row[32 + lane] = v1 - lse;
}

// ---------------------------------------------------------------------------
extern "C" void kernel_launch(void* const* d_in, const int* in_sizes, int n_in,
                              void* d_out, int out_size) {
    const float* x   = (const float*)d_in[0];
    const void*  ei  = d_in[1];
    const float* W1  = (const float*)d_in[2];
    const float* b1  = (const float*)d_in[3];
    const float* W2  = (const float*)d_in[4];
    const float* b2  = (const float*)d_in[5];
    float*       out = (float*)d_out;

    int n = in_sizes[0] / NFEAT;      // 100000
    int E = in_sizes[1] / 2;          // 3200000

    // normalize edge indices to int32 (robust to int64-vs-int32 harness layout)
    k_detect  <<<1, 1>>>(ei);
    k_convert <<<(E + 255) / 256, 256>>>(ei, E);

    // degrees + normalization
    k_deg_init <<<(n + 255) / 256, 256>>>(n);
    k_deg_count<<<(E + 255) / 256, 256>>>(E);
    k_dinv     <<<(n + 255) / 256, 256>>>(n);

    // layer 1
    dim3 g1((n + 127) / 128, NHID / 128);
    k_sgemm1   <<<g1, 256>>>(x, W1, n);
    k_init_agg1<<<((long long)n * 64 + 255) / 256, 256>>>(b1, n);
    long long w1threads = (long long)E * 32;
    k_scatter1 <<<(unsigned)((w1threads + 255) / 256), 256>>>(E);

    // layer 2
    k_gemm2    <<<((long long)n * 32 + 255) / 256, 256>>>(W2, n);
    k_init_out <<<((long long)n * 10 + 255) / 256, 256>>>(b2, out, n);
    k_scatter2 <<<(unsigned)(((long long)E * 10 + 255) / 256), 256>>>(out, E);

    // log_softmax
    k_logsoftmax<<<((long long)n * 32 + 255) / 256, 256>>>(out, n);
}

// round 6
// speedup vs baseline: 1.4411x; 1.4411x over previous
#include <cuda_runtime.h>
#include <cstdint>
#include <math.h>

#define NFEAT 512
#define NHID  256
#define NCLS  40
#define NMAX  100000
#define EMAX  3200000
#define NB_SCAN 128   // max scan blocks (ceil(1e5/1024)=98)

// ---- scratch (static device globals; allocation-free) ----
__device__ __align__(16) float g_dinv[NMAX];
__device__ __align__(16) float g_h1  [(size_t)NMAX * NHID];   // x @ W1
__device__ __align__(16) float g_agg1[(size_t)NMAX * NHID];   // relu(layer1 out)
__device__ __align__(16) float g_h2  [(size_t)NMAX * NCLS];   // agg1 @ W2
__device__ int g_src[EMAX];
__device__ int g_dst[EMAX];
__device__ int g_esrc[EMAX];            // CSR: src of edges grouped by dst
__device__ int g_cnt [NMAX];            // in-degree (excl self)
__device__ int g_fill[NMAX];            // fill cursors
__device__ int g_rowptr[NMAX + 1];
__device__ int g_bsum[NB_SCAN];
__device__ int g_boff[NB_SCAN];
__device__ int g_is64;

// ---------------------------------------------------------------------------
// edge dtype detection + normalization to int32
// ---------------------------------------------------------------------------
__global__ void k_detect(const void* __restrict__ ei) {
    const long long* p = (const long long*)ei;
    int i64 = 1;
    #pragma unroll
    for (int k = 0; k < 8; k++) {
        long long v = p[k];
        if (v < 0 || v >= NMAX) { i64 = 0; break; }
    }
    g_is64 = i64;
}

__global__ void k_convert(const void* __restrict__ ei, int E) {
    int e = blockIdx.x * blockDim.x + threadIdx.x;
    if (e >= E) return;
    if (g_is64) {
        const long long* p = (const long long*)ei;
        g_src[e] = (int)p[e];
        g_dst[e] = (int)p[E + e];
    } else {
        const int* p = (const int*)ei;
        g_src[e] = p[e];
        g_dst[e] = p[E + e];
    }
}

// ---------------------------------------------------------------------------
// degree histogram + dinv
// ---------------------------------------------------------------------------
__global__ void k_zero(int n) {
    int i = blockIdx.x * blockDim.x + threadIdx.x;
    if (i < n) { g_cnt[i] = 0; g_fill[i] = 0; }
}

__global__ void k_hist(int E) {
    int e = blockIdx.x * blockDim.x + threadIdx.x;
    if (e < E) atomicAdd(&g_cnt[g_dst[e]], 1);
}

__global__ void k_dinv(int n) {
    int i = blockIdx.x * blockDim.x + threadIdx.x;
    if (i < n) g_dinv[i] = rsqrtf((float)(g_cnt[i] + 1));   // +1 self-loop
}

// ---------------------------------------------------------------------------
// exclusive scan of g_cnt -> g_rowptr  (1024 elems / block)
// ---------------------------------------------------------------------------
__global__ __launch_bounds__(256) void k_scan1(int n) {
    __shared__ int ssum[256];
    int b = blockIdx.x, t = threadIdx.x;
    int base = b * 1024 + t * 4;
    int v0 = (base + 0 < n) ? g_cnt[base + 0] : 0;
    int v1 = (base + 1 < n) ? g_cnt[base + 1] : 0;
    int v2 = (base + 2 < n) ? g_cnt[base + 2] : 0;
    int v3 = (base + 3 < n) ? g_cnt[base + 3] : 0;
    int s = v0 + v1 + v2 + v3;
    ssum[t] = s;
    __syncthreads();
    for (int off = 1; off < 256; off <<= 1) {
        int x = (t >= off) ? ssum[t - off] : 0;
        __syncthreads();
        ssum[t] += x;
        __syncthreads();
    }
    int excl = ssum[t] - s;
    if (base + 0 < n) g_rowptr[base + 0] = excl;
    if (base + 1 < n) g_rowptr[base + 1] = excl + v0;
    if (base + 2 < n) g_rowptr[base + 2] = excl + v0 + v1;
    if (base + 3 < n) g_rowptr[base + 3] = excl + v0 + v1 + v2;
    if (t == 255) g_bsum[b] = ssum[255];
}

__global__ __launch_bounds__(NB_SCAN) void k_scan2(int nb) {
    __shared__ int sb[NB_SCAN];
    int t = threadIdx.x;
    int orig = (t < nb) ? g_bsum[t] : 0;
    sb[t] = orig;
    __syncthreads();
    for (int off = 1; off < NB_SCAN; off <<= 1) {
        int x = (t >= off) ? sb[t - off] : 0;
        __syncthreads();
        sb[t] += x;
        __syncthreads();
    }
    if (t < nb) g_boff[t] = sb[t] - orig;   // exclusive
}

__global__ void k_scan3(int n, int E) {
    int i = blockIdx.x * blockDim.x + threadIdx.x;
    if (i < n) g_rowptr[i] += g_boff[i >> 10];
    if (i == 0) g_rowptr[n] = E;
}

__global__ void k_fill(int E) {
    int e = blockIdx.x * blockDim.x + threadIdx.x;
    if (e >= E) return;
    int d = g_dst[e];
    int pos = g_rowptr[d] + atomicAdd(&g_fill[d], 1);
    g_esrc[pos] = g_src[e];
}

// ---------------------------------------------------------------------------
// SGEMM1: h1 = x @ W1  (M x 512)@(512 x 256), 128x128x16 double-buffered
// ---------------------------------------------------------------------------
__global__ __launch_bounds__(256) void k_sgemm1(const float* __restrict__ A,
                                                const float* __restrict__ B,
                                                int M) {
    const int K = NFEAT, N = NHID;
    __shared__ float As[2][16][128];
    __shared__ float Bs[2][16][128];

    int tid = threadIdx.x;
    int bm = blockIdx.x * 128;
    int bn = blockIdx.y * 128;
    int tx = tid % 16, ty = tid / 16;

    int aRow = tid >> 1;            // 0..127
    int aC   = (tid & 1) * 8;       // k-offset within tile: 0 or 8
    int bRow = tid >> 4;            // 0..15
    int bC   = (tid & 15) * 8;      // 0..120

    int gr = bm + aRow;
    const float* Ap = A + (size_t)gr * K;

    float acc[8][8];
    #pragma unroll
    for (int i = 0; i < 8; i++)
        #pragma unroll
        for (int j = 0; j < 8; j++) acc[i][j] = 0.0f;

    float4 pa0, pa1, pb0, pb1;

    // --- load tile 0 directly to smem ---
    {
        if (gr < M) { pa0 = *(const float4*)(Ap + aC); pa1 = *(const float4*)(Ap + aC + 4); }
        else        { pa0 = pa1 = make_float4(0.f, 0.f, 0.f, 0.f); }
        pb0 = *(const float4*)(B + (size_t)bRow * N + bn + bC);
        pb1 = *(const float4*)(B + (size_t)bRow * N + bn + bC + 4);
        As[0][aC + 0][aRow] = pa0.x; As[0][aC + 1][aRow] = pa0.y;
        As[0][aC + 2][aRow] = pa0.z; As[0][aC + 3][aRow] = pa0.w;
        As[0][aC + 4][aRow] = pa1.x; As[0][aC + 5][aRow] = pa1.y;
        As[0][aC + 6][aRow] = pa1.z; As[0][aC + 7][aRow] = pa1.w;
        *(float4*)&Bs[0][bRow][bC]     = pb0;
        *(float4*)&Bs[0][bRow][bC + 4] = pb1;
    }
    __syncthreads();

    int cur = 0;
    const int NT = K / 16;          // 32
    for (int t = 0; t < NT; t++) {
        if (t < NT - 1) {
            int k0 = (t + 1) * 16;
            if (gr < M) { pa0 = *(const float4*)(Ap + k0 + aC); pa1 = *(const float4*)(Ap + k0 + aC + 4); }
            else        { pa0 = pa1 = make_float4(0.f, 0.f, 0.f, 0.f); }
            pb0 = *(const float4*)(B + (size_t)(k0 + bRow) * N + bn + bC);
            pb1 = *(const float4*)(B + (size_t)(k0 + bRow) * N + bn + bC + 4);
        }
        #pragma unroll
        for (int kk = 0; kk < 16; kk++) {
            float ar[8], br[8];
            #pragma unroll
            for (int i = 0; i < 8; i++) ar[i] = As[cur][kk][ty * 8 + i];
            #pragma unroll
            for (int j = 0; j < 8; j++) br[j] = Bs[cur][kk][tx * 8 + j];
            #pragma unroll
            for (int i = 0; i < 8; i++)
                #pragma unroll
                for (int j = 0; j < 8; j++)
                    acc[i][j] = fmaf(ar[i], br[j], acc[i][j]);
        }
        if (t < NT - 1) {
            int nxt = cur ^ 1;
            As[nxt][aC + 0][aRow] = pa0.x; As[nxt][aC + 1][aRow] = pa0.y;
            As[nxt][aC + 2][aRow] = pa0.z; As[nxt][aC + 3][aRow] = pa0.w;
            As[nxt][aC + 4][aRow] = pa1.x; As[nxt][aC + 5][aRow] = pa1.y;
            As[nxt][aC + 6][aRow] = pa1.z; As[nxt][aC + 7][aRow] = pa1.w;
            *(float4*)&Bs[nxt][bRow][bC]     = pb0;
            *(float4*)&Bs[nxt][bRow][bC + 4] = pb1;
            __syncthreads();
            cur = nxt;
        }
    }

    #pragma unroll
    for (int i = 0; i < 8; i++) {
        int r = bm + ty * 8 + i;
        if (r >= M) continue;
        #pragma unroll
        for (int j = 0; j < 8; j += 4) {
            float4 v = make_float4(acc[i][j], acc[i][j+1], acc[i][j+2], acc[i][j+3]);
            *(float4*)(g_h1 + (size_t)r * N + tx * 8 + j + bn) = v;
        }
    }
}

// ---------------------------------------------------------------------------
// layer-1 aggregation (CSR, warp per node), bias+self folded, relu at store
// ---------------------------------------------------------------------------
__global__ __launch_bounds__(256) void k_agg1(const float* __restrict__ b1, int n) {
    int w    = (blockIdx.x * blockDim.x + threadIdx.x) >> 5;
    int lane = threadIdx.x & 31;
    if (w >= n) return;

    float wd = g_dinv[w];
    float w2 = wd * wd;
    int c0 = lane * 4, c1 = (lane + 32) * 4;

    float4 a0 = *(const float4*)(b1 + c0);
    float4 a1 = *(const float4*)(b1 + c1);
    {
        float4 h0 = *(const float4*)(g_h1 + (size_t)w * NHID + c0);
        float4 h1v = *(const float4*)(g_h1 + (size_t)w * NHID + c1);
        a0.x = fmaf(h0.x,  w2, a0.x); a0.y = fmaf(h0.y,  w2, a0.y);
        a0.z = fmaf(h0.z,  w2, a0.z); a0.w = fmaf(h0.w,  w2, a0.w);
        a1.x = fmaf(h1v.x, w2, a1.x); a1.y = fmaf(h1v.y, w2, a1.y);
        a1.z = fmaf(h1v.z, w2, a1.z); a1.w = fmaf(h1v.w, w2, a1.w);
    }

    int e = g_rowptr[w], end = g_rowptr[w + 1];
    for (; e + 1 < end; e += 2) {
        int s0 = g_esrc[e], s1 = g_esrc[e + 1];
        float n0 = g_dinv[s0] * wd, n1 = g_dinv[s1] * wd;
        const float* p0 = g_h1 + (size_t)s0 * NHID;
        const float* p1 = g_h1 + (size_t)s1 * NHID;
        float4 u0 = *(const float4*)(p0 + c0);
        float4 u1 = *(const float4*)(p0 + c1);
        float4 v0 = *(const float4*)(p1 + c0);
        float4 v1 = *(const float4*)(p1 + c1);
        a0.x = fmaf(u0.x, n0, fmaf(v0.x, n1, a0.x));
        a0.y = fmaf(u0.y, n0, fmaf(v0.y, n1, a0.y));
        a0.z = fmaf(u0.z, n0, fmaf(v0.z, n1, a0.z));
        a0.w = fmaf(u0.w, n0, fmaf(v0.w, n1, a0.w));
        a1.x = fmaf(u1.x, n0, fmaf(v1.x, n1, a1.x));
        a1.y = fmaf(u1.y, n0, fmaf(v1.y, n1, a1.y));
        a1.z = fmaf(u1.z, n0, fmaf(v1.z, n1, a1.z));
        a1.w = fmaf(u1.w, n0, fmaf(v1.w, n1, a1.w));
    }
    if (e < end) {
        int s0 = g_esrc[e];
        float n0 = g_dinv[s0] * wd;
        const float* p0 = g_h1 + (size_t)s0 * NHID;
        float4 u0 = *(const float4*)(p0 + c0);
        float4 u1 = *(const float4*)(p0 + c1);
        a0.x = fmaf(u0.x, n0, a0.x); a0.y = fmaf(u0.y, n0, a0.y);
        a0.z = fmaf(u0.z, n0, a0.z); a0.w = fmaf(u0.w, n0, a0.w);
        a1.x = fmaf(u1.x, n0, a1.x); a1.y = fmaf(u1.y, n0, a1.y);
        a1.z = fmaf(u1.z, n0, a1.z); a1.w = fmaf(u1.w, n0, a1.w);
    }

    // relu at store
    a0.x = fmaxf(a0.x, 0.f); a0.y = fmaxf(a0.y, 0.f);
    a0.z = fmaxf(a0.z, 0.f); a0.w = fmaxf(a0.w, 0.f);
    a1.x = fmaxf(a1.x, 0.f); a1.y = fmaxf(a1.y, 0.f);
    a1.z = fmaxf(a1.z, 0.f); a1.w = fmaxf(a1.w, 0.f);
    *(float4*)(g_agg1 + (size_t)w * NHID + c0) = a0;
    *(float4*)(g_agg1 + (size_t)w * NHID + c1) = a1;
}

// ---------------------------------------------------------------------------
// GEMM2: h2 = agg1 @ W2   (256 -> 40), warp per node (agg1 already relu'ed)
// ---------------------------------------------------------------------------
__global__ __launch_bounds__(256) void k_gemm2(const float* __restrict__ W2, int n) {
    __shared__ float Ws[NHID * NCLS];   // 40 KB
    int tid = threadIdx.x;
    for (int t = tid; t < NHID * NCLS; t += blockDim.x) Ws[t] = W2[t];
    __syncthreads();

    int warp = (blockIdx.x * blockDim.x + tid) >> 5;
    int lane = tid & 31;
    if (warp >= n) return;

    const float* row = g_agg1 + (size_t)warp * NHID;
    float acc0 = 0.f, acc1 = 0.f;
    for (int k0 = 0; k0 < NHID; k0 += 32) {
        float a = row[k0 + lane];
        #pragma unroll
        for (int kk = 0; kk < 32; kk++) {
            float av = __shfl_sync(0xffffffffu, a, kk);
            acc0 = fmaf(av, Ws[(k0 + kk) * NCLS + lane], acc0);
            if (lane < 8)
                acc1 = fmaf(av, Ws[(k0 + kk) * NCLS + 32 + lane], acc1);
        }
    }
    g_h2[(size_t)warp * NCLS + lane] = acc0;
    if (lane < 8) g_h2[(size_t)warp * NCLS + 32 + lane] = acc1;
}

// ---------------------------------------------------------------------------
// layer-2 aggregation + bias + self + log_softmax, fully fused. warp per node.
// lanes: sub = lane/10 (3 edges in flight), chunk = lane%10 (float4 of 40)
// ---------------------------------------------------------------------------
__global__ __launch_bounds__(256) void k_agg2(const float* __restrict__ b2,
                                              float* __restrict__ out, int n) {
    int w    = (blockIdx.x * blockDim.x + threadIdx.x) >> 5;
    int lane = threadIdx.x & 31;
    if (w >= n) return;

    float wd = g_dinv[w];
    int sub   = lane / 10;          // 0..2 (3 for lanes 30,31)
    int chunk = lane - sub * 10;    // 0..9

    float4 acc = make_float4(0.f, 0.f, 0.f, 0.f);
    int base = g_rowptr[w], end = g_rowptr[w + 1];
    for (int e = base; e < end; e += 3) {
        int ee = e + sub;
        if (sub < 3 && ee < end) {
            int s = g_esrc[ee];
            float nr = g_dinv[s];
            float4 v = *(const float4*)(g_h2 + (size_t)s * NCLS + chunk * 4);
            acc.x = fmaf(v.x, nr, acc.x);
            acc.y = fmaf(v.y, nr, acc.y);
            acc.z = fmaf(v.z, nr, acc.z);
            acc.w = fmaf(v.w, nr, acc.w);
        }
    }
    // fold sub=1,2 into sub=0 lanes (lane < 10)
    acc.x += __shfl_sync(0xffffffffu, acc.x, lane + 10) + __shfl_sync(0xffffffffu, acc.x, lane + 20);
    acc.y += __shfl_sync(0xffffffffu, acc.y, lane + 10) + __shfl_sync(0xffffffffu, acc.y, lane + 20);
    acc.z += __shfl_sync(0xffffffffu, acc.z, lane + 10) + __shfl_sync(0xffffffffu, acc.z, lane + 20);
    acc.w += __shfl_sync(0xffffffffu, acc.w, lane + 10) + __shfl_sync(0xffffffffu, acc.w, lane + 20);

    float4 val = make_float4(0.f, 0.f, 0.f, 0.f);
    if (lane < 10) {
        float4 self = *(const float4*)(g_h2 + (size_t)w * NCLS + lane * 4);
        float4 bv   = *(const float4*)(b2 + lane * 4);
        float w2 = wd * wd;
        val.x = bv.x + acc.x * wd + self.x * w2;
        val.y = bv.y + acc.y * wd + self.y * w2;
        val.z = bv.z + acc.z * wd + self.z * w2;
        val.w = bv.w + acc.w * wd + self.w * w2;
    }

    // log-softmax across the 40 values (lanes 0..9 hold them)
    float m = (lane < 10) ? fmaxf(fmaxf(val.x, val.y), fmaxf(val.z, val.w)) : -INFINITY;
    #pragma unroll
    for (int off = 16; off > 0; off >>= 1)
        m = fmaxf(m, __shfl_xor_sync(0xffffffffu, m, off));
    float es = (lane < 10)
             ? (__expf(val.x - m) + __expf(val.y - m) + __expf(val.z - m) + __expf(val.w - m))
             : 0.f;
    #pragma unroll
    for (int off = 16; off > 0; off >>= 1)
        es += __shfl_xor_sync(0xffffffffu, es, off);
    float lse = m + __logf(es);

    if (lane < 10) {
        float4 o = make_float4(val.x - lse, val.y - lse, val.z - lse, val.w - lse);
        *(float4*)(out + (size_t)w * NCLS + lane * 4) = o;
    }
}

// ---------------------------------------------------------------------------
extern "C" void kernel_launch(void* const* d_in, const int* in_sizes, int n_in,
                              void* d_out, int out_size) {
    const float* x   = (const float*)d_in[0];
    const void*  ei  = d_in[1];
    const float* W1  = (const float*)d_in[2];
    const float* b1  = (const float*)d_in[3];
    const float* W2  = (const float*)d_in[4];
    const float* b2  = (const float*)d_in[5];
    float*       out = (float*)d_out;

    int n = in_sizes[0] / NFEAT;      // 100000
    int E = in_sizes[1] / 2;          // 3200000
    int nb = (n + 1023) / 1024;

    // edge normalization + CSR build
    k_detect <<<1, 1>>>(ei);
    k_convert<<<(E + 255) / 256, 256>>>(ei, E);
    k_zero   <<<(n + 255) / 256, 256>>>(n);
    k_hist   <<<(E + 255) / 256, 256>>>(E);
    k_dinv   <<<(n + 255) / 256, 256>>>(n);
    k_scan1  <<<nb, 256>>>(n);
    k_scan2  <<<1, NB_SCAN>>>(nb);
    k_scan3  <<<(n + 255) / 256, 256>>>(n, E);
    k_fill   <<<(E + 255) / 256, 256>>>(E);

    // layer 1
    dim3 g1((n + 127) / 128, NHID / 128);
    k_sgemm1<<<g1, 256>>>(x, W1, n);
    k_agg1  <<<(unsigned)(((long long)n * 32 + 255) / 256), 256>>>(b1, n);

    // layer 2 (agg + bias + self + log_softmax fused)
    k_gemm2 <<<(unsigned)(((long long)n * 32 + 255) / 256), 256>>>(W2, n);
    k_agg2  <<<(unsigned)(((long long)n * 32 + 255) / 256), 256>>>(b2, out, n);
}